// round 14
// baseline (speedup 1.0000x reference)
#include <cuda_runtime.h>
#include <cuda_bf16.h>

// Cross-head online Hadamard — float2 + warp-shuffle split + software-pipelined
// persistent warps (register double buffering, corrected ping-pong).
//
// 32-point WHT across heads (stride 128 floats) per (token, d), scale 1/sqrt(32).
// Each thread holds 16 heads (one half) of its float2 column:
//   lane = g*16 + dp ; stages s=1..8 in registers, s=16 via shfl.xor(16).
//
// Grid-stride loop, 2-deep register double buffer: loads of the NEXT token are
// issued before compute+store of the CURRENT token. Invariant: every load16
// into a buffer is followed by exactly one wht_store of that buffer before the
// buffer is reused.

#define HIDDEN     4096
#define NUM_HEADS  32
#define HEAD_DIM   128
#define H_HALF     16
#define TOK_PER_BLOCK 2          // 8 warps = 2 tokens per block-iteration
#define GRID_CTAS  1184          // 8 * 148 SMs

__device__ __forceinline__ void load16(float2 v[H_HALF], const float2* __restrict__ p)
{
    #pragma unroll
    for (int j = 0; j < H_HALF; ++j)
        v[j] = __ldcs(p + j * (HEAD_DIM / 2));
}

__device__ __forceinline__ void wht_store(float2 v[H_HALF],
                                          float2* __restrict__ q,
                                          float sgn)
{
    // In-register WHT stages s = 1,2,4,8 over 16 contiguous heads.
    #pragma unroll
    for (int s = 1; s < H_HALF; s <<= 1) {
        #pragma unroll
        for (int j = 0; j < H_HALF; ++j) {
            if ((j & s) == 0) {
                const float2 a = v[j];
                const float2 b = v[j + s];
                v[j].x     = a.x + b.x;
                v[j].y     = a.y + b.y;
                v[j + s].x = a.x - b.x;
                v[j + s].y = a.y - b.y;
            }
        }
    }

    // Final stage s = 16 across the half-split: partner at lane ^ 16.
    // g=0: new = v + other ; g=1: new = other - v   (sgn = +/-1)
    #pragma unroll
    for (int j = 0; j < H_HALF; ++j) {
        const float ox = __shfl_xor_sync(0xffffffffu, v[j].x, 16);
        const float oy = __shfl_xor_sync(0xffffffffu, v[j].y, 16);
        v[j].x = fmaf(sgn, v[j].x, ox);
        v[j].y = fmaf(sgn, v[j].y, oy);
    }

    const float scale = 0.17677669529663687f;  // 1/sqrt(32)

    #pragma unroll
    for (int j = 0; j < H_HALF; ++j) {
        float2 r;
        r.x = v[j].x * scale;
        r.y = v[j].y * scale;
        __stcs(q + j * (HEAD_DIM / 2), r);
    }
}

__global__ __launch_bounds__(256, 2)
void cross_head_hadamard_pipe_kernel(const float2* __restrict__ x,
                                     float2* __restrict__ y,
                                     int num_tokens)
{
    const int warp = threadIdx.x >> 5;
    const int lane = threadIdx.x & 31;
    const int g    = lane >> 4;            // head half 0/1
    const int dp   = lane & 15;            // float2 column within chunk
    const int chunk = warp & 3;            // 0..3 (16 float2 each = 128 d total)
    const int local_tok = warp >> 2;       // 0..1

    // within-token float2 offset of this thread's first element (head g*16)
    const long long woff = (long long)g * H_HALF * (HEAD_DIM / 2)
                         + chunk * H_HALF + dp;
    const float sgn = (g == 0) ? 1.0f : -1.0f;

    int t = blockIdx.x * TOK_PER_BLOCK + local_tok;
    const int ts = gridDim.x * TOK_PER_BLOCK;   // token stride
    if (t >= num_tokens) return;

    float2 va[H_HALF], vb[H_HALF];

    // Prologue: fill buffer A with token t.
    load16(va, x + (long long)t * (HIDDEN / 2) + woff);

    // Ping-pong: each phase loads the NEXT token into the idle buffer, then
    // computes+stores the CURRENT token from the full buffer.
    for (;;) {
        // Phase A: va holds token t.
        int nxt = t + ts;
        if (nxt >= num_tokens) {
            wht_store(va, y + (long long)t * (HIDDEN / 2) + woff, sgn);
            return;
        }
        load16(vb, x + (long long)nxt * (HIDDEN / 2) + woff);
        wht_store(va, y + (long long)t * (HIDDEN / 2) + woff, sgn);
        t = nxt;

        // Phase B: vb holds token t.
        nxt = t + ts;
        if (nxt >= num_tokens) {
            wht_store(vb, y + (long long)t * (HIDDEN / 2) + woff, sgn);
            return;
        }
        load16(va, x + (long long)nxt * (HIDDEN / 2) + woff);
        wht_store(vb, y + (long long)t * (HIDDEN / 2) + woff, sgn);
        t = nxt;
    }
}

extern "C" void kernel_launch(void* const* d_in, const int* in_sizes, int n_in,
                              void* d_out, int out_size)
{
    const float2* x = (const float2*)d_in[0];
    float2*       y = (float2*)d_out;

    const int total_elems = in_sizes[0];           // 67,108,864
    const int num_tokens  = total_elems / HIDDEN;  // 16384

    cross_head_hadamard_pipe_kernel<<<GRID_CTAS, 256>>>(x, y, num_tokens);
}